// round 1
// baseline (speedup 1.0000x reference)
#include <cuda_runtime.h>
#include <math.h>

#define EMAX 4096
#define CAP (EMAX*(EMAX-1)/2)   // 8386560 worst-case pairs

// ---- device scratch (no allocations allowed) ----
__device__ float g_ang[EMAX];
__device__ float g_nx[EMAX], g_ny[EMAX], g_c[EMAX], g_mx[EMAX], g_my[EMAX];
__device__ unsigned int g_count;
__device__ float g_buf[CAP];                 // compacted masked distances (~33.5 MB)
__device__ unsigned int g_hist[3*256];       // radix-select histograms (3 ranks)
__device__ unsigned int g_prefix[3];         // bit-prefix of k-th smallest, per rank
__device__ unsigned int g_rank[3];           // remaining rank within prefix class
__device__ double g_sum;

#define PI_F  3.14159274101257324f
#define THR_F 0.08726646259971647f           /* radians(5.0), rounds to f32 like jnp */

// ---------------------------------------------------------------------------
// Kernel 1: per-edge geometry (E = 4096)
// ---------------------------------------------------------------------------
__global__ void k_setup(const float* __restrict__ pos, const int* __restrict__ eidx, int E)
{
    int e = blockIdx.x * blockDim.x + threadIdx.x;
    if (e == 0) { g_count = 0u; g_sum = 0.0; }
    if (e >= E) return;

    int s = eidx[e];
    int d = eidx[E + e];
    float sx = pos[2*s], sy = pos[2*s+1];
    float dx = pos[2*d], dy = pos[2*d+1];
    float vx = dx - sx, vy = dy - sy;
    float len = sqrtf(vx*vx + vy*vy);
    len = fmaxf(len, 1e-8f);
    float ux = vx / len, uy = vy / len;

    // angle in [0, pi): python-style floor-mod of atan2
    float a = atan2f(uy, ux);
    a = fmodf(a, PI_F);
    if (a < 0.f) a += PI_F;
    g_ang[e] = a;

    float nx = -uy, ny = ux;                 // normal of edge e
    g_nx[e] = nx;  g_ny[e] = ny;
    g_c[e]  = sx*nx + sy*ny;                 // line offset
    g_mx[e] = (sx + dx) * 0.5f;              // midpoint
    g_my[e] = (sy + dy) * 0.5f;
}

// ---------------------------------------------------------------------------
// Kernel 2: upper-triangle pair sweep with warp-aggregated compaction.
// Block i scans j in (i, E). dist(i,j) = |n_i . mid_j - c_i|  (asymmetric, as ref).
// ---------------------------------------------------------------------------
__global__ void k_pairs(int E)
{
    int i = blockIdx.x;
    float ai  = g_ang[i];
    float nxi = g_nx[i], nyi = g_ny[i], ci = g_c[i];

    for (int jb = i + 1; jb < E; jb += blockDim.x) {
        int j = jb + threadIdx.x;
        bool  m = false;
        float dist = 0.f;
        if (j < E) {
            float aj   = g_ang[j];
            float da   = fabsf(ai - aj);
            float circ = fminf(da, PI_F - da);
            if (circ <= THR_F) {
                m = true;
                dist = fabsf(fmaf(nxi, g_mx[j], fmaf(nyi, g_my[j], -ci)));
            }
        }
        unsigned ball = __ballot_sync(0xFFFFFFFFu, m);
        if (ball) {
            int lane   = threadIdx.x & 31;
            int leader = __ffs(ball) - 1;
            unsigned base = 0;
            if (lane == leader) base = atomicAdd(&g_count, (unsigned)__popc(ball));
            base = __shfl_sync(0xFFFFFFFFu, base, leader);
            if (m) {
                unsigned off = __popc(ball & ((1u << lane) - 1u));
                g_buf[base + off] = dist;
            }
        }
    }
}

// ---------------------------------------------------------------------------
// Kernel 3: initialize the three selection ranks from n (device-side; n only
// known after k_pairs). Ranks match the reference indexing exactly.
// ---------------------------------------------------------------------------
__global__ void k_init_select()
{
    if (threadIdx.x == 0) {
        int n  = (int)g_count;
        int r0 = n/4 - 1;      if (r0 < 0)     r0 = 0;       // q1 index
        int r1 = n/2;                                         // median index
        int r2 = (3*n)/4;      if (r2 > n - 1) r2 = n - 1;    // q3 index
        if (r2 < 0) r2 = 0;
        g_rank[0] = (unsigned)r0;
        g_rank[1] = (unsigned)r1;
        g_rank[2] = (unsigned)r2;
        g_prefix[0] = g_prefix[1] = g_prefix[2] = 0u;
    }
    __syncthreads();
    for (int t = threadIdx.x; t < 768; t += blockDim.x) g_hist[t] = 0u;
}

// ---------------------------------------------------------------------------
// Kernel 4: radix-select histogram pass (8 bits). Non-negative floats are
// order-isomorphic to their uint32 bit patterns, so this yields EXACT order
// statistics (bit-identical to sorting).
// ---------------------------------------------------------------------------
__global__ void k_hist(int shift)
{
    __shared__ unsigned sh[768];
    for (int t = threadIdx.x; t < 768; t += blockDim.x) sh[t] = 0u;
    __syncthreads();

    unsigned n     = g_count;
    unsigned pmask = (shift == 24) ? 0u : (0xFFFFFFFFu << (shift + 8));
    unsigned p0 = g_prefix[0], p1 = g_prefix[1], p2 = g_prefix[2];

    for (unsigned idx = blockIdx.x * blockDim.x + threadIdx.x; idx < n;
         idx += gridDim.x * blockDim.x) {
        unsigned bits = __float_as_uint(g_buf[idx]);
        unsigned hi   = bits & pmask;
        unsigned b    = (bits >> shift) & 255u;
        if (hi == p0) atomicAdd(&sh[b],       1u);
        if (hi == p1) atomicAdd(&sh[256 + b], 1u);
        if (hi == p2) atomicAdd(&sh[512 + b], 1u);
    }
    __syncthreads();
    for (int t = threadIdx.x; t < 768; t += blockDim.x) {
        unsigned v = sh[t];
        if (v) atomicAdd(&g_hist[t], v);
    }
}

// ---------------------------------------------------------------------------
// Kernel 5: pick the bucket containing each rank; narrow prefix; zero hists.
// ---------------------------------------------------------------------------
__global__ void k_reduce(int shift)
{
    if (threadIdx.x == 0) {
        for (int s = 0; s < 3; s++) {
            unsigned r = g_rank[s];
            unsigned cum = 0;
            int sel = 255;
            for (int b = 0; b < 256; b++) {
                unsigned h = g_hist[s*256 + b];
                if (cum + h > r) { sel = b; break; }
                cum += h;
            }
            g_prefix[s] |= ((unsigned)sel) << shift;
            g_rank[s]    = r - cum;
        }
    }
    __syncthreads();
    for (int t = threadIdx.x; t < 768; t += blockDim.x) g_hist[t] = 0u;
}

// ---------------------------------------------------------------------------
// Kernel 6: hinge-loss sum over the compacted distances (double accumulate).
// ---------------------------------------------------------------------------
__global__ void k_loss()
{
    unsigned n = g_count;
    float q1 = __uint_as_float(g_prefix[0]);
    float mu = __uint_as_float(g_prefix[1]);
    float q3 = __uint_as_float(g_prefix[2]);
    float margin = fmaxf(q3 - q1, 1e-6f) * 0.75f;   // iqr * 0.5 * 1.5

    double local = 0.0;
    for (unsigned idx = blockIdx.x * blockDim.x + threadIdx.x; idx < n;
         idx += gridDim.x * blockDim.x) {
        float d = g_buf[idx];
        float v = fabsf(d - mu) - margin;
        if (v > 0.f) local += (double)v;
    }

    // warp + block reduce
    for (int o = 16; o; o >>= 1) local += __shfl_down_sync(0xFFFFFFFFu, local, o);
    __shared__ double shs[32];
    if ((threadIdx.x & 31) == 0) shs[threadIdx.x >> 5] = local;
    __syncthreads();
    if (threadIdx.x < 32) {
        double v = (threadIdx.x < (blockDim.x + 31) / 32) ? shs[threadIdx.x] : 0.0;
        for (int o = 16; o; o >>= 1) v += __shfl_down_sync(0xFFFFFFFFu, v, o);
        if (threadIdx.x == 0 && v != 0.0) atomicAdd(&g_sum, v);
    }
}

// ---------------------------------------------------------------------------
// Kernel 7: finalize scalar output.
// ---------------------------------------------------------------------------
__global__ void k_final(float* __restrict__ out)
{
    unsigned n = g_count;
    double denom = (double)(n > 0u ? n : 1u);
    out[0] = (float)(g_sum / denom);
}

// ---------------------------------------------------------------------------
extern "C" void kernel_launch(void* const* d_in, const int* in_sizes, int n_in,
                              void* d_out, int out_size)
{
    const float* pos  = (const float*)d_in[0];   // node_positions (B*N, 2)
    // d_in[1] = adjacency: unused by the math
    const int*   eidx = (const int*)d_in[2];     // edge_index (2, E)
    float* out = (float*)d_out;

    int E = in_sizes[2] / 2;
    if (E > EMAX) E = EMAX;

    k_setup<<<(E + 255) / 256, 256>>>(pos, eidx, E);
    k_pairs<<<E, 256>>>(E);
    k_init_select<<<1, 256>>>();
    for (int shift = 24; shift >= 0; shift -= 8) {
        k_hist<<<256, 256>>>(shift);
        k_reduce<<<1, 256>>>(shift);
    }
    k_loss<<<256, 256>>>();
    k_final<<<1, 1>>>(out);
}

// round 2
// speedup vs baseline: 2.3398x; 2.3398x over previous
#include <cuda_runtime.h>
#include <math.h>

#define EMAX 4096
#define CAP (EMAX*(EMAX-1)/2)   // 8386560 worst-case pairs

// ---- device scratch (no allocations allowed) ----
__device__ float g_ang[EMAX];
__device__ float g_nx[EMAX], g_ny[EMAX], g_c[EMAX], g_mx[EMAX], g_my[EMAX];
__device__ float g_sang[EMAX];               // angle-sorted angles
__device__ unsigned short g_sidx[EMAX];      // original edge index per sorted slot
__device__ unsigned int g_count;
__device__ float g_buf[CAP];                 // compacted masked distances
__device__ unsigned int g_hist[3*256];       // radix-select histograms (3 ranks)
__device__ unsigned int g_prefix[3];         // bit-prefix of k-th smallest, per rank
__device__ unsigned int g_rank[3];           // remaining rank within prefix class
__device__ double g_sum;

#define PI_F  3.14159274101257324f
#define THR_F 0.08726646259971647f           /* radians(5.0) in f32 */

// ---------------------------------------------------------------------------
// Kernel 1: per-edge geometry (E = 4096)
// ---------------------------------------------------------------------------
__global__ void k_setup(const float* __restrict__ pos, const int* __restrict__ eidx, int E)
{
    int e = blockIdx.x * blockDim.x + threadIdx.x;
    if (e == 0) { g_count = 0u; g_sum = 0.0; }
    if (e >= E) return;

    int s = eidx[e];
    int d = eidx[E + e];
    float sx = pos[2*s], sy = pos[2*s+1];
    float dx = pos[2*d], dy = pos[2*d+1];
    float vx = dx - sx, vy = dy - sy;
    float len = sqrtf(vx*vx + vy*vy);
    len = fmaxf(len, 1e-8f);
    float ux = vx / len, uy = vy / len;

    // angle in [0, pi): python-style floor-mod of atan2
    float a = atan2f(uy, ux);
    a = fmodf(a, PI_F);
    if (a < 0.f) a += PI_F;
    g_ang[e] = a;

    float nx = -uy, ny = ux;
    g_nx[e] = nx;  g_ny[e] = ny;
    g_c[e]  = sx*nx + sy*ny;
    g_mx[e] = (sx + dx) * 0.5f;
    g_my[e] = (sy + dy) * 0.5f;
}

// ---------------------------------------------------------------------------
// Kernel 2: bitonic sort of (angle, idx), single block, shared memory.
// ---------------------------------------------------------------------------
__global__ void k_sort(int E)
{
    __shared__ float sa[EMAX];
    __shared__ unsigned short si[EMAX];

    for (int t = threadIdx.x; t < EMAX; t += blockDim.x) {
        sa[t] = (t < E) ? g_ang[t] : 3.4e38f;
        si[t] = (unsigned short)t;
    }
    __syncthreads();

    for (int k = 2; k <= EMAX; k <<= 1) {
        for (int j = k >> 1; j > 0; j >>= 1) {
            for (int t = threadIdx.x; t < EMAX; t += blockDim.x) {
                int p = t ^ j;
                if (p > t) {
                    bool up = ((t & k) == 0);
                    float va = sa[t], vb = sa[p];
                    if ((va > vb) == up) {
                        sa[t] = vb; sa[p] = va;
                        unsigned short ia = si[t]; si[t] = si[p]; si[p] = ia;
                    }
                }
            }
            __syncthreads();
        }
    }
    for (int t = threadIdx.x; t < EMAX; t += blockDim.x) {
        g_sang[t] = sa[t];
        g_sidx[t] = si[t];
    }
}

// ---------------------------------------------------------------------------
// Kernel 3: sorted pair sweep. One warp per sorted edge i.
// Qualifying j (sorted, j>i) form a contiguous prefix (da<=THR) and a
// contiguous suffix (da>THR && PI-da<=THR); exact disjoint partition of
// fminf(da, PI-da) <= THR.  dist uses the ORIGINAL lower-index edge's line.
// ---------------------------------------------------------------------------
__device__ __forceinline__ void emit_warp(unsigned full, bool in, float dist, int lane)
{
    unsigned ball = __ballot_sync(full, in);
    if (ball) {
        int leader = __ffs(ball) - 1;
        unsigned base = 0;
        if (lane == leader) base = atomicAdd(&g_count, (unsigned)__popc(ball));
        base = __shfl_sync(full, base, leader);
        if (in) g_buf[base + __popc(ball & ((1u << lane) - 1u))] = dist;
    }
}

__global__ void k_pairs2(int E)
{
    const unsigned FULL = 0xFFFFFFFFu;
    int wpb  = blockDim.x >> 5;
    int i    = blockIdx.x * wpb + (threadIdx.x >> 5);
    int lane = threadIdx.x & 31;
    if (i >= E - 1) return;

    float ai = g_sang[i];
    int   oi = g_sidx[i];

    // forward prefix: da <= THR
    for (int jb = i + 1; jb < E; jb += 32) {
        int  j     = jb + lane;
        bool valid = (j < E);
        bool in    = false;
        float dist = 0.f;
        if (valid) {
            float aj = g_sang[j];
            float da = fabsf(ai - aj);
            if (da <= THR_F) {
                in = true;
                int oj = (int)g_sidx[j];
                int a = min(oi, oj), b = max(oi, oj);
                dist = fabsf(fmaf(g_nx[a], g_mx[b], fmaf(g_ny[a], g_my[b], -g_c[a])));
            }
        }
        emit_warp(FULL, in, dist, lane);
        if (__any_sync(FULL, !in)) break;   // monotone: first failure ends prefix
    }

    // backward suffix: da > THR && PI - da <= THR
    for (int jb = E - 1; jb > i; jb -= 32) {
        int  j     = jb - lane;
        bool valid = (j > i);
        bool in    = false;
        bool stop  = true;
        float dist = 0.f;
        if (valid) {
            float aj = g_sang[j];
            float da = fabsf(ai - aj);
            stop = ((PI_F - da) > THR_F);
            if (!stop && da > THR_F) {
                in = true;
                int oj = (int)g_sidx[j];
                int a = min(oi, oj), b = max(oi, oj);
                dist = fabsf(fmaf(g_nx[a], g_mx[b], fmaf(g_ny[a], g_my[b], -g_c[a])));
            }
        }
        emit_warp(FULL, in, dist, lane);
        if (__any_sync(FULL, stop)) break;  // monotone: first failure ends suffix
    }
}

// ---------------------------------------------------------------------------
// Kernel 4: init selection ranks (reference indexing) + zero histograms.
// ---------------------------------------------------------------------------
__global__ void k_init_select()
{
    if (threadIdx.x == 0) {
        int n  = (int)g_count;
        int r0 = n/4 - 1;      if (r0 < 0)     r0 = 0;
        int r1 = n/2;
        int r2 = (3*n)/4;      if (r2 > n - 1) r2 = n - 1;
        if (r2 < 0) r2 = 0;
        g_rank[0] = (unsigned)r0;
        g_rank[1] = (unsigned)r1;
        g_rank[2] = (unsigned)r2;
        g_prefix[0] = g_prefix[1] = g_prefix[2] = 0u;
    }
    __syncthreads();
    for (int t = threadIdx.x; t < 768; t += blockDim.x) g_hist[t] = 0u;
}

// ---------------------------------------------------------------------------
// Kernel 5: radix-select histogram pass (exact: f32 >= 0 order == uint order).
// ---------------------------------------------------------------------------
__global__ void k_hist(int shift)
{
    __shared__ unsigned sh[768];
    for (int t = threadIdx.x; t < 768; t += blockDim.x) sh[t] = 0u;
    __syncthreads();

    unsigned n     = g_count;
    unsigned pmask = (shift == 24) ? 0u : (0xFFFFFFFFu << (shift + 8));
    unsigned p0 = g_prefix[0], p1 = g_prefix[1], p2 = g_prefix[2];

    for (unsigned idx = blockIdx.x * blockDim.x + threadIdx.x; idx < n;
         idx += gridDim.x * blockDim.x) {
        unsigned bits = __float_as_uint(g_buf[idx]);
        unsigned hi   = bits & pmask;
        unsigned b    = (bits >> shift) & 255u;
        if (hi == p0) atomicAdd(&sh[b],       1u);
        if (hi == p1) atomicAdd(&sh[256 + b], 1u);
        if (hi == p2) atomicAdd(&sh[512 + b], 1u);
    }
    __syncthreads();
    for (int t = threadIdx.x; t < 768; t += blockDim.x) {
        unsigned v = sh[t];
        if (v) atomicAdd(&g_hist[t], v);
    }
}

// ---------------------------------------------------------------------------
// Kernel 6: PARALLEL bucket selection. 256 threads, shared-memory inclusive
// scan per statistic; the unique thread with exc <= r < inc picks the bucket.
// ---------------------------------------------------------------------------
__global__ void k_reduce(int shift)
{
    __shared__ unsigned scan[256];
    int t = threadIdx.x;

    for (int s = 0; s < 3; s++) {
        unsigned h = g_hist[s*256 + t];
        unsigned r = g_rank[s];
        scan[t] = h;
        __syncthreads();
        #pragma unroll
        for (int off = 1; off < 256; off <<= 1) {
            unsigned v   = scan[t];
            unsigned add = (t >= off) ? scan[t - off] : 0u;
            __syncthreads();
            scan[t] = v + add;
            __syncthreads();
        }
        unsigned inc = scan[t], exc = inc - h;
        if (exc <= r && r < inc) {
            g_prefix[s] |= ((unsigned)t) << shift;
            g_rank[s]    = r - exc;
        }
        __syncthreads();
    }
    for (int k = t; k < 768; k += 256) g_hist[k] = 0u;
}

// ---------------------------------------------------------------------------
// Kernel 7: hinge-loss sum (double accumulate).
// ---------------------------------------------------------------------------
__global__ void k_loss()
{
    unsigned n = g_count;
    float q1 = __uint_as_float(g_prefix[0]);
    float mu = __uint_as_float(g_prefix[1]);
    float q3 = __uint_as_float(g_prefix[2]);
    float margin = fmaxf(q3 - q1, 1e-6f) * 0.75f;   // iqr * 0.5 * 1.5

    double local = 0.0;
    for (unsigned idx = blockIdx.x * blockDim.x + threadIdx.x; idx < n;
         idx += gridDim.x * blockDim.x) {
        float d = g_buf[idx];
        float v = fabsf(d - mu) - margin;
        if (v > 0.f) local += (double)v;
    }

    for (int o = 16; o; o >>= 1) local += __shfl_down_sync(0xFFFFFFFFu, local, o);
    __shared__ double shs[32];
    if ((threadIdx.x & 31) == 0) shs[threadIdx.x >> 5] = local;
    __syncthreads();
    if (threadIdx.x < 32) {
        double v = (threadIdx.x < (blockDim.x + 31) / 32) ? shs[threadIdx.x] : 0.0;
        for (int o = 16; o; o >>= 1) v += __shfl_down_sync(0xFFFFFFFFu, v, o);
        if (threadIdx.x == 0 && v != 0.0) atomicAdd(&g_sum, v);
    }
}

// ---------------------------------------------------------------------------
// Kernel 8: finalize scalar output.
// ---------------------------------------------------------------------------
__global__ void k_final(float* __restrict__ out)
{
    unsigned n = g_count;
    double denom = (double)(n > 0u ? n : 1u);
    out[0] = (float)(g_sum / denom);
}

// ---------------------------------------------------------------------------
extern "C" void kernel_launch(void* const* d_in, const int* in_sizes, int n_in,
                              void* d_out, int out_size)
{
    const float* pos  = (const float*)d_in[0];   // node_positions (B*N, 2)
    // d_in[1] = adjacency: unused by the math
    const int*   eidx = (const int*)d_in[2];     // edge_index (2, E)
    float* out = (float*)d_out;

    int E = in_sizes[2] / 2;
    if (E > EMAX) E = EMAX;

    k_setup<<<(E + 255) / 256, 256>>>(pos, eidx, E);
    k_sort<<<1, 1024>>>(E);
    k_pairs2<<<(E + 7) / 8, 256>>>(E);           // 8 warps/block, 1 warp per edge
    k_init_select<<<1, 256>>>();
    for (int shift = 24; shift >= 0; shift -= 8) {
        k_hist<<<256, 256>>>(shift);
        k_reduce<<<1, 256>>>(shift);
    }
    k_loss<<<256, 256>>>();
    k_final<<<1, 1>>>(out);
}